// round 5
// baseline (speedup 1.0000x reference)
#include <cuda_runtime.h>
#include <math.h>
#include <stdint.h>

#define BATCH 8
#define CD 512
#define ND 4096
#define MD 1024

// Scratch (device globals: allocation-free, graph-capturable)
__device__ float g_q[BATCH * CD * ND];              // 64 MiB
__device__ float g_k[BATCH * CD * MD];              // 16 MiB
__device__ float g_v[BATCH * CD * MD];              // 16 MiB
__device__ float g_e[(size_t)BATCH * ND * MD];      // 128 MiB

__device__ __forceinline__ float to_tf32(float x) {
    unsigned u;
    asm("cvt.rna.tf32.f32 %0, %1;" : "=r"(u) : "f"(x));
    return __uint_as_float(u);
}

__device__ __forceinline__ void mma8(float c[4], const float a[4], const float b[2]) {
    const unsigned* A = reinterpret_cast<const unsigned*>(a);
    const unsigned* B = reinterpret_cast<const unsigned*>(b);
    asm volatile(
        "mma.sync.aligned.m16n8k8.row.col.f32.tf32.tf32.f32 "
        "{%0,%1,%2,%3}, {%4,%5,%6,%7}, {%8,%9}, {%0,%1,%2,%3};\n"
        : "+f"(c[0]), "+f"(c[1]), "+f"(c[2]), "+f"(c[3])
        : "r"(A[0]), "r"(A[1]), "r"(A[2]), "r"(A[3]),
          "r"(B[0]), "r"(B[1]));
}

// Generic C[M,N] = alpha * A x B (+C if ACC), all fp32 global, tf32 mma compute.
// TRA: A element (m,k) at A[k*lda + m]  (else A[m*lda + k])
// TRB: B element (k,n) at B[n*ldb + k]  (else B[k*ldb + n])
// All dims assumed multiples of the tile (true for every shape here).
template <int TRA, int TRB, int ACC>
__global__ __launch_bounds__(256) void gemm_tf32(
    const float* __restrict__ Ag, const float* __restrict__ Bg,
    float* __restrict__ Cg,
    int Kdim, int lda, int ldb, int ldc,
    long long sA, long long sB, long long sC, float alpha)
{
    __shared__ float As[16][136];   // [k][m], stride 136 -> conflict-free frags
    __shared__ float Bs[16][136];   // [k][n]

    const float* Ab = Ag + (long long)blockIdx.z * sA;
    const float* Bb = Bg + (long long)blockIdx.z * sB;
    float*       Cb = Cg + (long long)blockIdx.z * sC;

    const int n0 = blockIdx.x * 128;
    const int m0 = blockIdx.y * 128;
    const int tid  = threadIdx.x;
    const int warp = tid >> 5;
    const int lane = tid & 31;
    const int wm = (warp & 3) * 32;   // 4 warps along M
    const int wn = (warp >> 2) * 64;  // 2 warps along N
    const int g  = lane >> 2;         // groupID
    const int tg = lane & 3;          // threadID_in_group

    float acc[2][8][4];
#pragma unroll
    for (int i = 0; i < 2; i++)
#pragma unroll
        for (int j = 0; j < 8; j++)
#pragma unroll
            for (int l = 0; l < 4; l++) acc[i][j][l] = 0.f;

    for (int kb = 0; kb < Kdim; kb += 16) {
        // ---- stage A tile (128 x 16) ----
#pragma unroll
        for (int i = tid; i < 128 * 16; i += 256) {
            int m, k; float v;
            if (TRA) { m = i & 127; k = i >> 7; v = Ab[(size_t)(kb + k) * lda + (m0 + m)]; }
            else     { k = i & 15;  m = i >> 4; v = Ab[(size_t)(m0 + m) * lda + (kb + k)]; }
            As[k][m] = to_tf32(v);
        }
        // ---- stage B tile (16 x 128) ----
#pragma unroll
        for (int i = tid; i < 128 * 16; i += 256) {
            int n, k; float v;
            if (TRB) { k = i & 15;  n = i >> 4; v = Bb[(size_t)(n0 + n) * ldb + (kb + k)]; }
            else     { n = i & 127; k = i >> 7; v = Bb[(size_t)(kb + k) * ldb + (n0 + n)]; }
            Bs[k][n] = to_tf32(v);
        }
        __syncthreads();

#pragma unroll
        for (int ks = 0; ks < 16; ks += 8) {
            float a[2][4];
#pragma unroll
            for (int mt = 0; mt < 2; mt++) {
                int r = wm + mt * 16 + g;
                a[mt][0] = As[ks + tg][r];          // (g,     tg)
                a[mt][1] = As[ks + tg][r + 8];      // (g+8,   tg)
                a[mt][2] = As[ks + tg + 4][r];      // (g,     tg+4)
                a[mt][3] = As[ks + tg + 4][r + 8];  // (g+8,   tg+4)
            }
            float b[8][2];
#pragma unroll
            for (int nt = 0; nt < 8; nt++) {
                int c = wn + nt * 8 + g;
                b[nt][0] = Bs[ks + tg][c];          // (tg,   g)
                b[nt][1] = Bs[ks + tg + 4][c];      // (tg+4, g)
            }
#pragma unroll
            for (int mt = 0; mt < 2; mt++)
#pragma unroll
                for (int nt = 0; nt < 8; nt++)
                    mma8(acc[mt][nt], a[mt], b[nt]);
        }
        __syncthreads();
    }

    // ---- epilogue ----
#pragma unroll
    for (int mt = 0; mt < 2; mt++) {
        int r = m0 + wm + mt * 16 + g;
#pragma unroll
        for (int nt = 0; nt < 8; nt++) {
            int c = n0 + wn + nt * 8 + tg * 2;
            float2* p0 = reinterpret_cast<float2*>(Cb + (size_t)r * ldc + c);
            float2* p1 = reinterpret_cast<float2*>(Cb + (size_t)(r + 8) * ldc + c);
            float2 v0 = make_float2(alpha * acc[mt][nt][0], alpha * acc[mt][nt][1]);
            float2 v1 = make_float2(alpha * acc[mt][nt][2], alpha * acc[mt][nt][3]);
            if (ACC) {
                float2 o0 = *p0, o1 = *p1;
                v0.x += o0.x; v0.y += o0.y;
                v1.x += o1.x; v1.y += o1.y;
            }
            *p0 = v0;
            *p1 = v1;
        }
    }
}

// Row-wise softmax over M=1024, one block (256 threads) per row, in place.
__global__ __launch_bounds__(256) void softmax_k(float* __restrict__ E) {
    __shared__ float redm[8];
    __shared__ float reds[8];
    float4* rp = reinterpret_cast<float4*>(E + (size_t)blockIdx.x * MD);
    float4 v = rp[threadIdx.x];

    float mx = fmaxf(fmaxf(v.x, v.y), fmaxf(v.z, v.w));
#pragma unroll
    for (int o = 16; o; o >>= 1) mx = fmaxf(mx, __shfl_xor_sync(0xffffffffu, mx, o));
    if ((threadIdx.x & 31) == 0) redm[threadIdx.x >> 5] = mx;
    __syncthreads();
    mx = redm[0];
#pragma unroll
    for (int i = 1; i < 8; i++) mx = fmaxf(mx, redm[i]);

    v.x = __expf(v.x - mx);
    v.y = __expf(v.y - mx);
    v.z = __expf(v.z - mx);
    v.w = __expf(v.w - mx);

    float s = v.x + v.y + v.z + v.w;
#pragma unroll
    for (int o = 16; o; o >>= 1) s += __shfl_xor_sync(0xffffffffu, s, o);
    if ((threadIdx.x & 31) == 0) reds[threadIdx.x >> 5] = s;
    __syncthreads();
    s = reds[0];
#pragma unroll
    for (int i = 1; i < 8; i++) s += reds[i];

    float inv = 1.f / s;
    v.x *= inv; v.y *= inv; v.z *= inv; v.w *= inv;
    rp[threadIdx.x] = v;
}

extern "C" void kernel_launch(void* const* d_in, const int* in_sizes, int n_in,
                              void* d_out, int out_size) {
    (void)in_sizes; (void)n_in; (void)out_size;
    const float* pcd_up   = (const float*)d_in[0];
    const float* pcd_down = (const float*)d_in[1];
    const float* Wq    = (const float*)d_in[2];
    const float* Wk    = (const float*)d_in[3];
    const float* Wv    = (const float*)d_in[4];
    const float* Wskip = (const float*)d_in[5];
    float* out = (float*)d_out;

    float *q, *k, *v, *e;
    cudaGetSymbolAddress((void**)&q, g_q);
    cudaGetSymbolAddress((void**)&k, g_k);
    cudaGetSymbolAddress((void**)&v, g_v);
    cudaGetSymbolAddress((void**)&e, g_e);

    const long long sUp = (long long)CD * ND;   // per-batch stride of [C,N]
    const long long sDn = (long long)CD * MD;   // per-batch stride of [C,M]
    const long long sE  = (long long)ND * MD;   // per-batch stride of [N,M]
    const float inv_sqrt_c = 1.0f / sqrtf((float)CD);

    dim3 blk(256);

    // q[b] = Wq x pcd_up[b]        (M=CD, N=ND, K=CD)
    dim3 gup(ND / 128, CD / 128, BATCH);
    gemm_tf32<0, 0, 0><<<gup, blk>>>(Wq, pcd_up, q, CD, CD, ND, ND, 0LL, sUp, sUp, 1.f);
    // skip -> out directly
    gemm_tf32<0, 0, 0><<<gup, blk>>>(Wskip, pcd_up, out, CD, CD, ND, ND, 0LL, sUp, sUp, 1.f);

    // k[b], v[b] = W x pcd_down[b] (M=CD, N=MD, K=CD)
    dim3 gdn(MD / 128, CD / 128, BATCH);
    gemm_tf32<0, 0, 0><<<gdn, blk>>>(Wk, pcd_down, k, CD, CD, MD, MD, 0LL, sDn, sDn, 1.f);
    gemm_tf32<0, 0, 0><<<gdn, blk>>>(Wv, pcd_down, v, CD, CD, MD, MD, 0LL, sDn, sDn, 1.f);

    // energy[b] = (q[b]^T x k[b]) / sqrt(C)   (M=ND rows n, N=MD cols m, K=CD)
    // A = q^T: element (n,c) at q[c*ND + n]  -> TRA, lda=ND
    dim3 ge(MD / 128, ND / 128, BATCH);
    gemm_tf32<1, 0, 0><<<ge, blk>>>(q, k, e, CD, ND, MD, MD, sUp, sDn, sE, inv_sqrt_c);

    // softmax over last dim (rows = B*N)
    softmax_k<<<BATCH * ND, 256>>>(e);

    // out[b] += v[b] x P[b]^T   (M=CD rows c, N=ND cols n, K=MD)
    // B = P^T: element (m,n) at e[n*MD + m] -> TRB, ldb=MD
    dim3 gx(ND / 128, CD / 128, BATCH);
    gemm_tf32<0, 1, 1><<<gx, blk>>>(v, e, out, MD, MD, MD, ND, sDn, sE, sUp, 1.f);
}

// round 7
// speedup vs baseline: 1.5275x; 1.5275x over previous
#include <cuda_runtime.h>
#include <math.h>
#include <stdint.h>

#define BATCH 8
#define CD 512
#define ND 4096
#define MD 1024

// Scratch (device globals: allocation-free, graph-capturable)
__device__ float g_q[BATCH * CD * ND];              // 64 MiB
__device__ float g_k[BATCH * CD * MD];              // 16 MiB
__device__ float g_v[BATCH * CD * MD];              // 16 MiB
__device__ float g_e[(size_t)BATCH * ND * MD];      // 128 MiB

__device__ __forceinline__ float to_tf32(float x) {
    unsigned u;
    asm("cvt.rna.tf32.f32 %0, %1;" : "=r"(u) : "f"(x));
    return __uint_as_float(u);
}

__device__ __forceinline__ void cp16(uint32_t saddr, const float* g) {
    asm volatile("cp.async.cg.shared.global [%0], [%1], 16;\n" :: "r"(saddr), "l"(g));
}
__device__ __forceinline__ void cp_commit() {
    asm volatile("cp.async.commit_group;\n");
}
template <int N> __device__ __forceinline__ void cp_wait() {
    asm volatile("cp.async.wait_group %0;\n" :: "n"(N));
}

__device__ __forceinline__ void mma8(float c[4], const float a[4], const float b[2]) {
    const unsigned* A = reinterpret_cast<const unsigned*>(a);
    const unsigned* B = reinterpret_cast<const unsigned*>(b);
    asm volatile(
        "mma.sync.aligned.m16n8k8.row.col.f32.tf32.tf32.f32 "
        "{%0,%1,%2,%3}, {%4,%5,%6,%7}, {%8,%9}, {%0,%1,%2,%3};\n"
        : "+f"(c[0]), "+f"(c[1]), "+f"(c[2]), "+f"(c[3])
        : "r"(A[0]), "r"(A[1]), "r"(A[2]), "r"(A[3]),
          "r"(B[0]), "r"(B[1]));
}

// ---------------------------------------------------------------------------
// C[M,N] = alpha * A x B (+C if ACC).  tf32 mma, cp.async double-buffered.
// TRA: A element (m,k) at A[k*lda + m]  (else A[m*lda + k])
// TRB: B element (k,n) at B[n*ldb + k]  (else B[k*ldb + n])
// CVTF: apply cvt.rna.tf32 on fragment loads (raw fp32 operands)
// CVTO: apply cvt.rna.tf32 to outputs before store (pre-round for consumers)
// BM=BN=128, BK=32.  All dims multiples of tiles (true for every call here).
// smem layouts (per stage), chosen so cp.async chunks are 16B-contiguous:
//   A: TRA -> [k][m] pad 132   | !TRA -> [m][k] pad 36
//   B: TRB -> [n][k] pad 36    | !TRB -> [k][n] pad 132
// ---------------------------------------------------------------------------
template <int TRA, int TRB, int ACC, int CVTF, int CVTO>
__global__ void __launch_bounds__(256, 2) gemm_tf32(
    const float* __restrict__ Ag, const float* __restrict__ Bg,
    float* __restrict__ Cg,
    int Kdim, int lda, int ldb, int ldc,
    long long sA, long long sB, long long sC, float alpha)
{
    constexpr int AF = TRA ? 32 * 132 : 128 * 36;
    constexpr int BF = TRB ? 128 * 36 : 32 * 132;
    constexpr int STG = AF + BF;
    extern __shared__ float sm[];

    const float* Ab = Ag + (long long)blockIdx.z * sA;
    const float* Bb = Bg + (long long)blockIdx.z * sB;
    float*       Cb = Cg + (long long)blockIdx.z * sC;

    const int n0 = blockIdx.x * 128;
    const int m0 = blockIdx.y * 128;
    const int tid  = threadIdx.x;
    const int warp = tid >> 5;
    const int lane = tid & 31;
    const int wm = (warp & 3) * 32;   // 4 warps along M
    const int wn = (warp >> 2) * 64;  // 2 warps along N
    const int g  = lane >> 2;
    const int tg = lane & 3;

    float acc[2][8][4];
#pragma unroll
    for (int i = 0; i < 2; i++)
#pragma unroll
        for (int j = 0; j < 8; j++)
#pragma unroll
            for (int l = 0; l < 4; l++) acc[i][j][l] = 0.f;

    // ---- async stage loader -------------------------------------------------
    auto load_stage = [&](int st, int kb) {
        uint32_t sa = (uint32_t)__cvta_generic_to_shared(sm + st * STG);
        uint32_t sb = sa + AF * 4;
#pragma unroll
        for (int it = 0; it < 4; it++) {
            int ci = tid + it * 256;
            if (TRA) {                 // [k][m]: 32 k-rows x 32 chunks of 4 m
                int k = ci >> 5, m4 = (ci & 31) << 2;
                cp16(sa + (k * 132 + m4) * 4, Ab + (size_t)(kb + k) * lda + m0 + m4);
            } else {                   // [m][k]: 128 m-rows x 8 chunks of 4 k
                int m = ci >> 3, k4 = (ci & 7) << 2;
                cp16(sa + (m * 36 + k4) * 4, Ab + (size_t)(m0 + m) * lda + kb + k4);
            }
        }
#pragma unroll
        for (int it = 0; it < 4; it++) {
            int ci = tid + it * 256;
            if (TRB) {                 // [n][k]
                int n = ci >> 3, k4 = (ci & 7) << 2;
                cp16(sb + (n * 36 + k4) * 4, Bb + (size_t)(n0 + n) * ldb + kb + k4);
            } else {                   // [k][n]
                int k = ci >> 5, n4 = (ci & 31) << 2;
                cp16(sb + (k * 132 + n4) * 4, Bb + (size_t)(kb + k) * ldb + n0 + n4);
            }
        }
    };

    // ---- compute one 32-deep stage -----------------------------------------
    auto compute_stage = [&](int st) {
        const float* As = sm + st * STG;
        const float* Bs = As + AF;
#pragma unroll
        for (int ks = 0; ks < 32; ks += 8) {
            float a[2][4];
#pragma unroll
            for (int mt = 0; mt < 2; mt++) {
                int r = wm + mt * 16 + g;
                if (TRA) {
                    a[mt][0] = As[(ks + tg) * 132 + r];
                    a[mt][1] = As[(ks + tg) * 132 + r + 8];
                    a[mt][2] = As[(ks + tg + 4) * 132 + r];
                    a[mt][3] = As[(ks + tg + 4) * 132 + r + 8];
                } else {
                    a[mt][0] = As[r * 36 + ks + tg];
                    a[mt][1] = As[(r + 8) * 36 + ks + tg];
                    a[mt][2] = As[r * 36 + ks + tg + 4];
                    a[mt][3] = As[(r + 8) * 36 + ks + tg + 4];
                }
                if (CVTF) {
#pragma unroll
                    for (int l = 0; l < 4; l++) a[mt][l] = to_tf32(a[mt][l]);
                }
            }
            float b[8][2];
#pragma unroll
            for (int nt = 0; nt < 8; nt++) {
                int c = wn + nt * 8 + g;
                if (TRB) {
                    b[nt][0] = Bs[c * 36 + ks + tg];
                    b[nt][1] = Bs[c * 36 + ks + tg + 4];
                } else {
                    b[nt][0] = Bs[(ks + tg) * 132 + c];
                    b[nt][1] = Bs[(ks + tg + 4) * 132 + c];
                }
                if (CVTF) {
                    b[nt][0] = to_tf32(b[nt][0]);
                    b[nt][1] = to_tf32(b[nt][1]);
                }
            }
#pragma unroll
            for (int mt = 0; mt < 2; mt++)
#pragma unroll
                for (int nt = 0; nt < 8; nt++)
                    mma8(acc[mt][nt], a[mt], b[nt]);
        }
    };

    // ---- pipelined mainloop -------------------------------------------------
    const int nk = Kdim >> 5;
    load_stage(0, 0);
    cp_commit();
    for (int i = 0; i < nk; i++) {
        if (i + 1 < nk) {
            load_stage((i + 1) & 1, (i + 1) << 5);
            cp_commit();
            cp_wait<1>();          // stage i resident
        } else {
            cp_wait<0>();
        }
        __syncthreads();
        compute_stage(i & 1);
        __syncthreads();           // protect buffer before next overwrite
    }

    // ---- epilogue -----------------------------------------------------------
#pragma unroll
    for (int mt = 0; mt < 2; mt++) {
        int r = m0 + wm + mt * 16 + g;
#pragma unroll
        for (int nt = 0; nt < 8; nt++) {
            int c = n0 + wn + nt * 8 + tg * 2;
            float2* p0 = reinterpret_cast<float2*>(Cb + (size_t)r * ldc + c);
            float2* p1 = reinterpret_cast<float2*>(Cb + (size_t)(r + 8) * ldc + c);
            float2 v0 = make_float2(alpha * acc[mt][nt][0], alpha * acc[mt][nt][1]);
            float2 v1 = make_float2(alpha * acc[mt][nt][2], alpha * acc[mt][nt][3]);
            if (CVTO) {
                v0.x = to_tf32(v0.x); v0.y = to_tf32(v0.y);
                v1.x = to_tf32(v1.x); v1.y = to_tf32(v1.y);
            }
            if (ACC) {
                float2 o0 = *p0, o1 = *p1;
                v0.x += o0.x; v0.y += o0.y;
                v1.x += o1.x; v1.y += o1.y;
            }
            *p0 = v0;
            *p1 = v1;
        }
    }
}

// Row-wise softmax over M=1024, one block (256 threads) per row, in place.
// Output probabilities are pre-rounded to tf32 (PV consumer skips cvt).
__global__ __launch_bounds__(256) void softmax_k(float* __restrict__ E) {
    __shared__ float redm[8];
    __shared__ float reds[8];
    float4* rp = reinterpret_cast<float4*>(E + (size_t)blockIdx.x * MD);
    float4 v = rp[threadIdx.x];

    float mx = fmaxf(fmaxf(v.x, v.y), fmaxf(v.z, v.w));
#pragma unroll
    for (int o = 16; o; o >>= 1) mx = fmaxf(mx, __shfl_xor_sync(0xffffffffu, mx, o));
    if ((threadIdx.x & 31) == 0) redm[threadIdx.x >> 5] = mx;
    __syncthreads();
    mx = redm[0];
#pragma unroll
    for (int i = 1; i < 8; i++) mx = fmaxf(mx, redm[i]);

    v.x = __expf(v.x - mx);
    v.y = __expf(v.y - mx);
    v.z = __expf(v.z - mx);
    v.w = __expf(v.w - mx);

    float s = v.x + v.y + v.z + v.w;
#pragma unroll
    for (int o = 16; o; o >>= 1) s += __shfl_xor_sync(0xffffffffu, s, o);
    if ((threadIdx.x & 31) == 0) reds[threadIdx.x >> 5] = s;
    __syncthreads();
    s = reds[0];
#pragma unroll
    for (int i = 1; i < 8; i++) s += reds[i];

    float inv = 1.f / s;
    v.x = to_tf32(v.x * inv);
    v.y = to_tf32(v.y * inv);
    v.z = to_tf32(v.z * inv);
    v.w = to_tf32(v.w * inv);
    rp[threadIdx.x] = v;
}

extern "C" void kernel_launch(void* const* d_in, const int* in_sizes, int n_in,
                              void* d_out, int out_size) {
    (void)in_sizes; (void)n_in; (void)out_size;
    const float* pcd_up   = (const float*)d_in[0];
    const float* pcd_down = (const float*)d_in[1];
    const float* Wq    = (const float*)d_in[2];
    const float* Wk    = (const float*)d_in[3];
    const float* Wv    = (const float*)d_in[4];
    const float* Wskip = (const float*)d_in[5];
    float* out = (float*)d_out;

    float *q, *k, *v, *e;
    cudaGetSymbolAddress((void**)&q, g_q);
    cudaGetSymbolAddress((void**)&k, g_k);
    cudaGetSymbolAddress((void**)&v, g_v);
    cudaGetSymbolAddress((void**)&e, g_e);

    const long long sUp = (long long)CD * ND;
    const long long sDn = (long long)CD * MD;
    const long long sE  = (long long)ND * MD;
    const float inv_sqrt_c = 1.0f / sqrtf((float)CD);

    // Dynamic smem sizes per instantiation (2 stages)
    constexpr int SH_PROJ = 2 * (128 * 36 + 32 * 132) * 4;   // <0,0,...>  70656 B
    constexpr int SH_EN   = 2 * (32 * 132 + 32 * 132) * 4;   // <1,0,...>  67584 B
    constexpr int SH_PV   = 2 * (128 * 36 + 128 * 36) * 4;   // <0,1,...>  73728 B

    cudaFuncSetAttribute(gemm_tf32<0, 0, 0, 1, 1>,
                         cudaFuncAttributeMaxDynamicSharedMemorySize, SH_PROJ);
    cudaFuncSetAttribute(gemm_tf32<0, 0, 0, 1, 0>,
                         cudaFuncAttributeMaxDynamicSharedMemorySize, SH_PROJ);
    cudaFuncSetAttribute(gemm_tf32<1, 0, 0, 0, 0>,
                         cudaFuncAttributeMaxDynamicSharedMemorySize, SH_EN);
    cudaFuncSetAttribute(gemm_tf32<0, 1, 1, 0, 0>,
                         cudaFuncAttributeMaxDynamicSharedMemorySize, SH_PV);

    dim3 blk(256);

    // q[b] = Wq x pcd_up[b]  (outputs tf32-rounded for energy GEMM)
    dim3 gup(ND / 128, CD / 128, BATCH);
    gemm_tf32<0, 0, 0, 1, 1><<<gup, blk, SH_PROJ>>>(
        Wq, pcd_up, q, CD, CD, ND, ND, 0LL, sUp, sUp, 1.f);
    // skip -> out directly (full precision output)
    gemm_tf32<0, 0, 0, 1, 0><<<gup, blk, SH_PROJ>>>(
        Wskip, pcd_up, out, CD, CD, ND, ND, 0LL, sUp, sUp, 1.f);

    // k[b], v[b] = W x pcd_down[b] (tf32-rounded outputs)
    dim3 gdn(MD / 128, CD / 128, BATCH);
    gemm_tf32<0, 0, 0, 1, 1><<<gdn, blk, SH_PROJ>>>(
        Wk, pcd_down, k, CD, CD, MD, MD, 0LL, sDn, sDn, 1.f);
    gemm_tf32<0, 0, 0, 1, 1><<<gdn, blk, SH_PROJ>>>(
        Wv, pcd_down, v, CD, CD, MD, MD, 0LL, sDn, sDn, 1.f);

    // energy[b] = (q[b]^T x k[b]) / sqrt(C); operands already tf32 -> no cvt
    dim3 ge(MD / 128, ND / 128, BATCH);
    gemm_tf32<1, 0, 0, 0, 0><<<ge, blk, SH_EN>>>(
        q, k, e, CD, ND, MD, MD, sUp, sDn, sE, inv_sqrt_c);

    // softmax over last dim (rows = B*N), probs pre-rounded to tf32
    softmax_k<<<BATCH * ND, 256>>>(e);

    // out[b] += v[b] x P[b]^T ; operands already tf32 -> no cvt
    dim3 gx(ND / 128, CD / 128, BATCH);
    gemm_tf32<0, 1, 1, 0, 0><<<gx, blk, SH_PV>>>(
        v, e, out, MD, MD, MD, ND, sDn, sE, sUp, 1.f);
}

// round 13
// speedup vs baseline: 2.6944x; 1.7639x over previous
#include <cuda_runtime.h>
#include <cuda_bf16.h>
#include <math.h>
#include <stdint.h>

#define BATCH 8
#define CD 512
#define ND 4096
#define MD 1024

// ---------------------------------------------------------------------------
// Scratch (device globals: allocation-free, graph-capturable)
// ---------------------------------------------------------------------------
__device__ __nv_bfloat16 g_upT[(size_t)BATCH * ND * CD];   // pcd_up^T  bf16 [B][N][C]
__device__ __nv_bfloat16 g_dnT[(size_t)BATCH * MD * CD];   // pcd_down^T bf16 [B][M][C]
__device__ __nv_bfloat16 g_wb[3][CD * CD];                 // Wq, Wk, Wv bf16 [o][c]
__device__ __nv_bfloat16 g_qT[(size_t)BATCH * ND * CD];    // q^T bf16 [B][N][C]
__device__ __nv_bfloat16 g_kT[(size_t)BATCH * MD * CD];    // k^T bf16 [B][M][C]
__device__ __nv_bfloat16 g_v [(size_t)BATCH * CD * MD];    // v   bf16 [B][C][M]
__device__ float         g_e [(size_t)BATCH * ND * MD];    // energy fp32 [B][N][M]
__device__ __nv_bfloat16 g_p [(size_t)BATCH * ND * MD];    // softmax bf16 [B][N][M]

// ---------------------------------------------------------------------------
// helpers
// ---------------------------------------------------------------------------
__device__ __forceinline__ float to_tf32(float x) {
    unsigned u;
    asm("cvt.rna.tf32.f32 %0, %1;" : "=r"(u) : "f"(x));
    return __uint_as_float(u);
}
__device__ __forceinline__ void cp16(uint32_t saddr, const void* g) {
    asm volatile("cp.async.cg.shared.global [%0], [%1], 16;\n" :: "r"(saddr), "l"(g));
}
__device__ __forceinline__ void cp_commit() {
    asm volatile("cp.async.commit_group;\n");
}
template <int N> __device__ __forceinline__ void cp_wait() {
    asm volatile("cp.async.wait_group %0;\n" :: "n"(N));
}
__device__ __forceinline__ void ldsm4(uint32_t* r, uint32_t addr) {
    asm volatile("ldmatrix.sync.aligned.m8n8.x4.shared.b16 {%0,%1,%2,%3}, [%4];"
        : "=r"(r[0]), "=r"(r[1]), "=r"(r[2]), "=r"(r[3]) : "r"(addr));
}
__device__ __forceinline__ void mma16(float* c, const uint32_t* a, uint32_t b0, uint32_t b1) {
    asm volatile(
        "mma.sync.aligned.m16n8k16.row.col.f32.bf16.bf16.f32 "
        "{%0,%1,%2,%3}, {%4,%5,%6,%7}, {%8,%9}, {%0,%1,%2,%3};\n"
        : "+f"(c[0]), "+f"(c[1]), "+f"(c[2]), "+f"(c[3])
        : "r"(a[0]), "r"(a[1]), "r"(a[2]), "r"(a[3]), "r"(b0), "r"(b1));
}

// ---------------------------------------------------------------------------
// bf16 GEMM: C[Mrows,Ncols] = op( A[Mrows][K] x B[Ncols][K]^T )
// Both operands K-contiguous bf16 (ld = K). BM=BN=128, BK=32, 8 warps (4x2).
// MODE 0: C bf16 = D   MODE 1: C fp32 = alpha*D   MODE 2: C fp32 += D
// smem per stage: A 128 rows x 80B (32 bf16 + 8 pad), B same. 2 stages = 40 KB.
// ---------------------------------------------------------------------------
#define ROWB  80      // padded row stride in bytes (conflict-free: r*80 mod 128 perm)
#define OPB   (128 * ROWB)        // 10240 bytes per operand per stage
#define STGB  (2 * OPB)           // 20480 per stage

template <int MODE>
__global__ void __launch_bounds__(256, 2) gemm_bf16(
    const __nv_bfloat16* __restrict__ Ag, const __nv_bfloat16* __restrict__ Bg,
    void* __restrict__ Cg, int K, int ldc,
    long long sA, long long sB, long long sC, float alpha)
{
    __shared__ __align__(16) char sm[2 * STGB];
    const uint32_t smb = (uint32_t)__cvta_generic_to_shared(sm);

    const int n0 = blockIdx.x * 128;
    const int m0 = blockIdx.y * 128;
    const int tid  = threadIdx.x;
    const int warp = tid >> 5;
    const int lane = tid & 31;
    const int wm = (warp & 3) * 32;   // 4 warps along M
    const int wn = (warp >> 2) * 64;  // 2 warps along N
    const int g  = lane >> 2;
    const int tg = lane & 3;
    const int lrow = lane & 15;
    const int lhi  = (lane >> 4) * 16;

    const char* Ab = (const char*)(Ag + (long long)blockIdx.z * sA + (size_t)m0 * K);
    const char* Bb = (const char*)(Bg + (long long)blockIdx.z * sB + (size_t)n0 * K);

    float acc[2][8][4];
#pragma unroll
    for (int i = 0; i < 2; i++)
#pragma unroll
        for (int j = 0; j < 8; j++)
#pragma unroll
            for (int l = 0; l < 4; l++) acc[i][j][l] = 0.f;

    // ---- stage one BK=32 chunk (A 128x32 + B 128x32 bf16) ----
    auto stage = [&](int st, int kb) {
        const uint32_t sa = smb + st * STGB;
        const uint32_t sb = sa + OPB;
#pragma unroll
        for (int it = 0; it < 2; it++) {            // A: 512 x 16B, j-major
            int c = tid + it * 256;
            int j = c >> 7, r = c & 127;
            cp16(sa + r * ROWB + j * 16, Ab + ((size_t)r * K + kb) * 2 + j * 16);
        }
#pragma unroll
        for (int it = 0; it < 2; it++) {            // B: 512 x 16B
            int c = tid + it * 256;
            int j = c >> 7, r = c & 127;
            cp16(sb + r * ROWB + j * 16, Bb + ((size_t)r * K + kb) * 2 + j * 16);
        }
    };

    // ---- compute one stage (two k16 steps) ----
    auto compute = [&](int st) {
        const uint32_t sa = smb + st * STGB;
        const uint32_t sb = sa + OPB;
#pragma unroll
        for (int ks = 0; ks < 32; ks += 16) {
            uint32_t a[2][4];
#pragma unroll
            for (int mt = 0; mt < 2; mt++)
                ldsm4(a[mt], sa + (wm + mt * 16 + lrow) * ROWB + ks * 2 + lhi);
            uint32_t bb[4][4];
#pragma unroll
            for (int p = 0; p < 4; p++)
                ldsm4(bb[p], sb + (wn + p * 16 + lrow) * ROWB + ks * 2 + lhi);
#pragma unroll
            for (int mt = 0; mt < 2; mt++)
#pragma unroll
                for (int nt = 0; nt < 8; nt++)
                    mma16(acc[mt][nt], a[mt], bb[nt >> 1][nt & 1], bb[nt >> 1][2 + (nt & 1)]);
        }
    };

    const int nk = K >> 5;
    stage(0, 0);
    cp_commit();
    for (int i = 0; i < nk; i++) {
        if (i + 1 < nk) { stage((i + 1) & 1, (i + 1) << 5); cp_commit(); cp_wait<1>(); }
        else            { cp_wait<0>(); }
        __syncthreads();
        compute(i & 1);
        __syncthreads();
    }

    // ---- epilogue ----
#pragma unroll
    for (int mt = 0; mt < 2; mt++) {
        const int r = m0 + wm + mt * 16 + g;
#pragma unroll
        for (int nt = 0; nt < 8; nt++) {
            const int c = n0 + wn + nt * 8 + tg * 2;
            const float* a4 = acc[mt][nt];
            if (MODE == 0) {
                __nv_bfloat16* Cb = (__nv_bfloat16*)Cg + (long long)blockIdx.z * sC;
                __nv_bfloat162 h0 = __floats2bfloat162_rn(a4[0], a4[1]);
                __nv_bfloat162 h1 = __floats2bfloat162_rn(a4[2], a4[3]);
                *(uint32_t*)(Cb + (size_t)r * ldc + c)       = *(uint32_t*)&h0;
                *(uint32_t*)(Cb + (size_t)(r + 8) * ldc + c) = *(uint32_t*)&h1;
            } else if (MODE == 1) {
                float* Cb = (float*)Cg + (long long)blockIdx.z * sC;
                *(float2*)(Cb + (size_t)r * ldc + c) =
                    make_float2(alpha * a4[0], alpha * a4[1]);
                *(float2*)(Cb + (size_t)(r + 8) * ldc + c) =
                    make_float2(alpha * a4[2], alpha * a4[3]);
            } else {
                float* Cb = (float*)Cg + (long long)blockIdx.z * sC;
                float2* p0 = (float2*)(Cb + (size_t)r * ldc + c);
                float2* p1 = (float2*)(Cb + (size_t)(r + 8) * ldc + c);
                float2 o0 = *p0, o1 = *p1;
                o0.x += a4[0]; o0.y += a4[1];
                o1.x += a4[2]; o1.y += a4[3];
                *p0 = o0; *p1 = o1;
            }
        }
    }
}

// ---------------------------------------------------------------------------
// transpose + fp32->bf16: in fp32 [C=512][X] per batch -> out bf16 [X][512]
// ---------------------------------------------------------------------------
__global__ void __launch_bounds__(256) transpose_cvt(
    const float* __restrict__ in, __nv_bfloat16* __restrict__ out, int X)
{
    __shared__ float t[32][33];
    const float* ib = in + (size_t)blockIdx.z * CD * X;
    __nv_bfloat16* ob = out + (size_t)blockIdx.z * X * CD;
    const int x0 = blockIdx.x * 32, c0 = blockIdx.y * 32;
    const int tx = threadIdx.x, ty = threadIdx.y;
#pragma unroll
    for (int j = ty; j < 32; j += 8)
        t[j][tx] = ib[(size_t)(c0 + j) * X + x0 + tx];
    __syncthreads();
#pragma unroll
    for (int j = ty; j < 32; j += 8)
        ob[(size_t)(x0 + j) * CD + c0 + tx] = __float2bfloat16(t[tx][j]);
}

__global__ void __launch_bounds__(256) cvt_bf16(
    const float* __restrict__ in, __nv_bfloat16* __restrict__ out, int n)
{
    int i = blockIdx.x * 256 + threadIdx.x;
    if (i < n) out[i] = __float2bfloat16(in[i]);
}

// ---------------------------------------------------------------------------
// Row softmax over M=1024 (fp32 in, bf16 out)
// ---------------------------------------------------------------------------
__global__ void __launch_bounds__(256) softmax_k(
    const float* __restrict__ E, __nv_bfloat16* __restrict__ P)
{
    __shared__ float redm[8];
    __shared__ float reds[8];
    const float4* rp = reinterpret_cast<const float4*>(E + (size_t)blockIdx.x * MD);
    float4 v = rp[threadIdx.x];

    float mx = fmaxf(fmaxf(v.x, v.y), fmaxf(v.z, v.w));
#pragma unroll
    for (int o = 16; o; o >>= 1) mx = fmaxf(mx, __shfl_xor_sync(0xffffffffu, mx, o));
    if ((threadIdx.x & 31) == 0) redm[threadIdx.x >> 5] = mx;
    __syncthreads();
    mx = redm[0];
#pragma unroll
    for (int i = 1; i < 8; i++) mx = fmaxf(mx, redm[i]);

    v.x = __expf(v.x - mx); v.y = __expf(v.y - mx);
    v.z = __expf(v.z - mx); v.w = __expf(v.w - mx);

    float s = v.x + v.y + v.z + v.w;
#pragma unroll
    for (int o = 16; o; o >>= 1) s += __shfl_xor_sync(0xffffffffu, s, o);
    if ((threadIdx.x & 31) == 0) reds[threadIdx.x >> 5] = s;
    __syncthreads();
    s = reds[0];
#pragma unroll
    for (int i = 1; i < 8; i++) s += reds[i];

    const float inv = 1.f / s;
    __nv_bfloat162 h0 = __floats2bfloat162_rn(v.x * inv, v.y * inv);
    __nv_bfloat162 h1 = __floats2bfloat162_rn(v.z * inv, v.w * inv);
    uint2 u = make_uint2(*(uint32_t*)&h0, *(uint32_t*)&h1);
    reinterpret_cast<uint2*>(P + (size_t)blockIdx.x * MD)[threadIdx.x] = u;
}

// ---------------------------------------------------------------------------
// Legacy tf32 GEMM (skip path only — precision-critical)
// ---------------------------------------------------------------------------
__device__ __forceinline__ void mma8(float c[4], const float a[4], const float b[2]) {
    const unsigned* A = reinterpret_cast<const unsigned*>(a);
    const unsigned* B = reinterpret_cast<const unsigned*>(b);
    asm volatile(
        "mma.sync.aligned.m16n8k8.row.col.f32.tf32.tf32.f32 "
        "{%0,%1,%2,%3}, {%4,%5,%6,%7}, {%8,%9}, {%0,%1,%2,%3};\n"
        : "+f"(c[0]), "+f"(c[1]), "+f"(c[2]), "+f"(c[3])
        : "r"(A[0]), "r"(A[1]), "r"(A[2]), "r"(A[3]), "r"(B[0]), "r"(B[1]));
}

__global__ void __launch_bounds__(256, 2) skip_gemm(
    const float* __restrict__ Ag, const float* __restrict__ Bg,
    float* __restrict__ Cg, long long sB, long long sC)
{
    // C[128x128 tile of CD x ND] = Wskip(CD x CD) x pcd_up(CD x ND)
    constexpr int AF = 128 * 36;   // [m][k] pad 36
    constexpr int BF = 32 * 132;   // [k][n] pad 132
    constexpr int STG = AF + BF;
    extern __shared__ float smf[];

    const float* Bb = Bg + (long long)blockIdx.z * sB;
    float*       Cb = Cg + (long long)blockIdx.z * sC;

    const int n0 = blockIdx.x * 128;
    const int m0 = blockIdx.y * 128;
    const int tid  = threadIdx.x;
    const int warp = tid >> 5;
    const int lane = tid & 31;
    const int wm = (warp & 3) * 32;
    const int wn = (warp >> 2) * 64;
    const int g  = lane >> 2;
    const int tg = lane & 3;

    float acc[2][8][4];
#pragma unroll
    for (int i = 0; i < 2; i++)
#pragma unroll
        for (int j = 0; j < 8; j++)
#pragma unroll
            for (int l = 0; l < 4; l++) acc[i][j][l] = 0.f;

    auto load_stage = [&](int st, int kb) {
        uint32_t sa = (uint32_t)__cvta_generic_to_shared(smf + st * STG);
        uint32_t sb = sa + AF * 4;
#pragma unroll
        for (int it = 0; it < 4; it++) {
            int ci = tid + it * 256;
            int m = ci >> 3, k4 = (ci & 7) << 2;
            cp16(sa + (m * 36 + k4) * 4, Ag + (size_t)(m0 + m) * CD + kb + k4);
        }
#pragma unroll
        for (int it = 0; it < 4; it++) {
            int ci = tid + it * 256;
            int k = ci >> 5, n4 = (ci & 31) << 2;
            cp16(sb + (k * 132 + n4) * 4, Bb + (size_t)(kb + k) * ND + n0 + n4);
        }
    };

    auto compute_stage = [&](int st) {
        const float* As = smf + st * STG;
        const float* Bs = As + AF;
#pragma unroll
        for (int ks = 0; ks < 32; ks += 8) {
            float a[2][4];
#pragma unroll
            for (int mt = 0; mt < 2; mt++) {
                int r = wm + mt * 16 + g;
                a[mt][0] = to_tf32(As[r * 36 + ks + tg]);
                a[mt][1] = to_tf32(As[(r + 8) * 36 + ks + tg]);
                a[mt][2] = to_tf32(As[r * 36 + ks + tg + 4]);
                a[mt][3] = to_tf32(As[(r + 8) * 36 + ks + tg + 4]);
            }
            float b[8][2];
#pragma unroll
            for (int nt = 0; nt < 8; nt++) {
                int c = wn + nt * 8 + g;
                b[nt][0] = to_tf32(Bs[(ks + tg) * 132 + c]);
                b[nt][1] = to_tf32(Bs[(ks + tg + 4) * 132 + c]);
            }
#pragma unroll
            for (int mt = 0; mt < 2; mt++)
#pragma unroll
                for (int nt = 0; nt < 8; nt++)
                    mma8(acc[mt][nt], a[mt], b[nt]);
        }
    };

    const int nk = CD >> 5;
    load_stage(0, 0);
    cp_commit();
    for (int i = 0; i < nk; i++) {
        if (i + 1 < nk) { load_stage((i + 1) & 1, (i + 1) << 5); cp_commit(); cp_wait<1>(); }
        else            { cp_wait<0>(); }
        __syncthreads();
        compute_stage(i & 1);
        __syncthreads();
    }

#pragma unroll
    for (int mt = 0; mt < 2; mt++) {
        int r = m0 + wm + mt * 16 + g;
#pragma unroll
        for (int nt = 0; nt < 8; nt++) {
            int c = n0 + wn + nt * 8 + tg * 2;
            *(float2*)(Cb + (size_t)r * ND + c) =
                make_float2(acc[mt][nt][0], acc[mt][nt][1]);
            *(float2*)(Cb + (size_t)(r + 8) * ND + c) =
                make_float2(acc[mt][nt][2], acc[mt][nt][3]);
        }
    }
}

// ---------------------------------------------------------------------------
extern "C" void kernel_launch(void* const* d_in, const int* in_sizes, int n_in,
                              void* d_out, int out_size) {
    (void)in_sizes; (void)n_in; (void)out_size;
    const float* pcd_up   = (const float*)d_in[0];
    const float* pcd_down = (const float*)d_in[1];
    const float* Wq    = (const float*)d_in[2];
    const float* Wk    = (const float*)d_in[3];
    const float* Wv    = (const float*)d_in[4];
    const float* Wskip = (const float*)d_in[5];
    float* out = (float*)d_out;

    __nv_bfloat16 *upT, *dnT, *wb, *qT, *kT, *v, *p;
    float* e;
    cudaGetSymbolAddress((void**)&upT, g_upT);
    cudaGetSymbolAddress((void**)&dnT, g_dnT);
    cudaGetSymbolAddress((void**)&wb,  g_wb);
    cudaGetSymbolAddress((void**)&qT,  g_qT);
    cudaGetSymbolAddress((void**)&kT,  g_kT);
    cudaGetSymbolAddress((void**)&v,   g_v);
    cudaGetSymbolAddress((void**)&e,   g_e);
    cudaGetSymbolAddress((void**)&p,   g_p);
    __nv_bfloat16* wq = wb;
    __nv_bfloat16* wk = wb + CD * CD;
    __nv_bfloat16* wv = wb + 2 * CD * CD;

    constexpr int SH_SKIP = 2 * (128 * 36 + 32 * 132) * 4;
    cudaFuncSetAttribute(skip_gemm, cudaFuncAttributeMaxDynamicSharedMemorySize, SH_SKIP);

    const long long sUpT = (long long)ND * CD;
    const long long sDnT = (long long)MD * CD;
    const long long sV   = (long long)CD * MD;
    const long long sE   = (long long)ND * MD;
    const long long sOut = (long long)CD * ND;
    const float inv_sqrt_c = 1.0f / sqrtf((float)CD);

    // 1) transposed bf16 inputs + bf16 weights
    transpose_cvt<<<dim3(ND / 32, CD / 32, BATCH), dim3(32, 8)>>>(pcd_up, upT, ND);
    transpose_cvt<<<dim3(MD / 32, CD / 32, BATCH), dim3(32, 8)>>>(pcd_down, dnT, MD);
    cvt_bf16<<<CD * CD / 256, 256>>>(Wq, wq, CD * CD);
    cvt_bf16<<<CD * CD / 256, 256>>>(Wk, wk, CD * CD);
    cvt_bf16<<<CD * CD / 256, 256>>>(Wv, wv, CD * CD);

    // 2) skip -> out (tf32, precision-critical)
    skip_gemm<<<dim3(ND / 128, CD / 128, BATCH), 256, SH_SKIP>>>(
        Wskip, pcd_up, out, sUpT, sOut);

    // 3) qT[n][o] = upT x Wq^T   (M=ND, N=CD, K=CD)
    gemm_bf16<0><<<dim3(CD / 128, ND / 128, BATCH), 256>>>(
        upT, wq, qT, CD, CD, sUpT, 0LL, sUpT, 1.f);
    // 4) kT[m][o] = dnT x Wk^T   (M=MD, N=CD, K=CD)
    gemm_bf16<0><<<dim3(CD / 128, MD / 128, BATCH), 256>>>(
        dnT, wk, kT, CD, CD, sDnT, 0LL, sDnT, 1.f);
    // 5) v[o][m] = Wv x dnT^T    (M=CD, N=MD, K=CD)
    gemm_bf16<0><<<dim3(MD / 128, CD / 128, BATCH), 256>>>(
        wv, dnT, v, CD, MD, 0LL, sDnT, sV, 1.f);

    // 6) energy[n][m] = (qT x kT^T) / sqrt(C)  (M=ND, N=MD, K=CD) -> fp32
    gemm_bf16<1><<<dim3(MD / 128, ND / 128, BATCH), 256>>>(
        qT, kT, e, CD, MD, sUpT, sDnT, sE, inv_sqrt_c);

    // 7) softmax rows -> bf16 P
    softmax_k<<<BATCH * ND, 256>>>(e, p);

    // 8) out[c][n] += v x P^T    (M=CD, N=ND, K=MD)
    gemm_bf16<2><<<dim3(ND / 128, CD / 128, BATCH), 256>>>(
        v, p, out, MD, ND, sV, sE, sOut, 1.f);
}